// round 1
// baseline (speedup 1.0000x reference)
#include <cuda_runtime.h>
#include <cuda_bf16.h>

// DenseToSparse: x [B=32, C=64, H=128, W=128] f32 NCHW.
// Output: feats [B*H*W, C] = NHWC rows with active sites compacted to front
// (row-major site order preserved), tail rows zero, plus count appended.
//
// Single-pass stream compaction with decoupled lookback:
//   K1: reset tile descriptors + tile counter
//   K2: per-tile load(coalesced) -> flag -> block scan -> lookback -> scatter active rows
//   K3: zero tail rows (row >= nnz), write count

#define Bn 32
#define Cn 64
#define Hn 128
#define Wn 128
#define HWn (Hn * Wn)            // 16384
#define CHWn (Cn * HWn)          // 1048576
#define NSITES (Bn * HWn)        // 524288
#define NFEAT ((long long)NSITES * Cn)  // 33554432

#define TILE_SITES 128
#define NUM_TILES (NSITES / TILE_SITES) // 4096

#define FLAG_A (1u << 30)
#define FLAG_P (2u << 30)
#define VAL_MASK 0x3FFFFFFFu

__device__ unsigned g_status[NUM_TILES];
__device__ unsigned g_tileCounter;
__device__ int g_total;

__device__ __forceinline__ unsigned ldv(const unsigned* p) {
    return *(const volatile unsigned*)p;
}
__device__ __forceinline__ void stv(unsigned* p, unsigned v) {
    *(volatile unsigned*)p = v;
}

__global__ void d2s_init_kernel() {
    unsigned gid = blockIdx.x * blockDim.x + threadIdx.x;
    if (gid < NUM_TILES) g_status[gid] = 0u;
    if (gid == 0) { g_tileCounter = 0u; g_total = 0; }
}

__global__ __launch_bounds__(TILE_SITES) void d2s_scatter_kernel(
    const float* __restrict__ x, float* __restrict__ out)
{
    __shared__ float vals[TILE_SITES * 65];   // stride-65 padding: bank-conflict-free
    __shared__ unsigned rowOf[TILE_SITES];
    __shared__ unsigned wsum[TILE_SITES / 32];
    __shared__ unsigned s_tile, s_excl, s_agg;

    const int tid = threadIdx.x;
    const int lane = tid & 31;
    const int wid = tid >> 5;

    if (tid == 0) s_tile = atomicAdd(&g_tileCounter, 1u);
    __syncthreads();
    const unsigned tile = s_tile;

    // ---- load: each thread owns one site, loops over 64 channels ----
    const int site = (int)tile * TILE_SITES + tid;
    const int b = site >> 14;          // site / HW
    const int s = site & (HWn - 1);    // site % HW
    const float* p = x + (long long)b * CHWn + s;

    bool anyv = false;
#pragma unroll
    for (int c = 0; c < Cn; ++c) {
        float v = __ldg(p + c * HWn);  // lanes -> consecutive addrs: fully coalesced
        vals[tid * 65 + c] = v;
        anyv = anyv || (v != 0.0f);    // == (sum|x| != 0), incl. NaN active, -0 inactive
    }

    // ---- block exclusive scan of flags ----
    unsigned ballot = __ballot_sync(0xffffffffu, anyv);
    unsigned lanePref = __popc(ballot & ((1u << lane) - 1u));
    if (lane == 0) wsum[wid] = __popc(ballot);
    __syncthreads();
    if (tid == 0) {
        unsigned acc = 0;
#pragma unroll
        for (int i = 0; i < TILE_SITES / 32; ++i) {
            unsigned t = wsum[i]; wsum[i] = acc; acc += t;
        }
        s_agg = acc;
    }
    __syncthreads();
    const unsigned blockExcl = wsum[wid] + lanePref;
    const unsigned agg = s_agg;

    // ---- decoupled lookback (warp 0) ----
    if (wid == 0) {
        if (tile == 0) {
            if (lane == 0) {
                stv(&g_status[0], FLAG_P | agg);
                s_excl = 0u;
                if (NUM_TILES == 1) g_total = (int)agg;
            }
        } else {
            if (lane == 0) stv(&g_status[tile], FLAG_A | agg);
            unsigned excl = 0u;
            int t = (int)tile - 1;
            for (;;) {
                int idx = t - lane;
                unsigned st = (idx >= 0) ? ldv(&g_status[idx]) : FLAG_P;
                while (__any_sync(0xffffffffu, (st >> 30) == 0u)) {
                    if ((st >> 30) == 0u) st = ldv(&g_status[idx]);
                }
                unsigned pmask = __ballot_sync(0xffffffffu, (st >> 30) == 2u);
                if (pmask) {
                    int fp = __ffs(pmask) - 1;  // nearest predecessor with full prefix
                    unsigned contrib = (lane <= fp) ? (st & VAL_MASK) : 0u;
                    excl += __reduce_add_sync(0xffffffffu, contrib);
                    break;
                } else {
                    excl += __reduce_add_sync(0xffffffffu, st & VAL_MASK);
                    t -= 32;
                }
            }
            if (lane == 0) {
                s_excl = excl;
                stv(&g_status[tile], FLAG_P | (excl + agg));
                if (tile == NUM_TILES - 1) g_total = (int)(excl + agg);
            }
        }
    }
    __syncthreads();

    rowOf[tid] = anyv ? (s_excl + blockExcl) : 0xFFFFFFFFu;
    __syncthreads();

    // ---- cooperative scatter of active rows (coalesced 128B runs per warp) ----
#pragma unroll
    for (int k = 0; k < Cn; ++k) {
        int l = k * TILE_SITES + tid;       // over (site, channel) pairs
        int st = l >> 6;                    // site within tile
        int c = l & (Cn - 1);
        unsigned r = rowOf[st];
        if (r != 0xFFFFFFFFu)
            out[(long long)r * Cn + c] = vals[st * 65 + c];
    }
}

__global__ void d2s_tail_kernel(float* __restrict__ out, int write_count) {
    const int total = g_total;
    unsigned gid = blockIdx.x * blockDim.x + threadIdx.x;
    const unsigned nfeat4 = (unsigned)(NFEAT / 4);   // 8388608 float4s
    if (gid < nfeat4) {
        unsigned row = gid >> 4;                     // 16 float4 per 64-float row
        if ((int)row >= total)
            reinterpret_cast<float4*>(out)[gid] = make_float4(0.f, 0.f, 0.f, 0.f);
    }
    if (gid == 0 && write_count)
        out[NFEAT] = (float)total;
}

extern "C" void kernel_launch(void* const* d_in, const int* in_sizes, int n_in,
                              void* d_out, int out_size) {
    const float* x = (const float*)d_in[0];
    float* out = (float*)d_out;

    d2s_init_kernel<<<(NUM_TILES + 255) / 256, 256>>>();
    d2s_scatter_kernel<<<NUM_TILES, TILE_SITES>>>(x, out);

    int write_count = (out_size > (int)NFEAT || (long long)out_size > NFEAT) ? 1 : 0;
    unsigned nfeat4 = (unsigned)(NFEAT / 4);
    d2s_tail_kernel<<<(nfeat4 + 255) / 256, 256>>>(out, write_count);
}